// round 10
// baseline (speedup 1.0000x reference)
#include <cuda_runtime.h>
#include <math.h>

// Problem constants (fixed shapes per reference setup_inputs)
#define NB    2
#define NDIM  128          // D = H = W = 128
#define NC    4            // image channels
#define IMG_ELEMS (NB * NDIM * NDIM * NDIM * NC)   // 16777216

// Double-precision combined (Gauss o cubic-resize) 128x4 per-axis weights.
// Published by build_T2_kernel block (d=0,b=0) for use by warp_kernel.
__device__ double Mgd[NDIM][4];
// T2d[b][d][h][k][c] = sum_{i,j} M[d][i] M[h][j] coarse[b][i][j][k][c]  (f64)
__device__ double T2d[NB][NDIM][NDIM][4][3];

// ---------------------------------------------------------------------------
// Fused kernel: per block (d, b), 128 threads over h.
//  1. Build f32-quantized cubic-resize rows Rs[128][4] (one row per thread)
//     and f32-quantized Gaussian taps Gf[16] (threads 0..15), matching jax's
//     f64-compute -> f32-cast weight quantization.
//  2. Compose M rows in f64 from the f32 factors (zero-padded SAME conv):
//     per-thread Mh (row h) and Md (row d, redundant across threads).
//  3. Contract coarse flow over D,H axes in f64 -> T2d.
//  Block (d==0, b==0) additionally publishes Mgd[h] for warp_kernel.
// ---------------------------------------------------------------------------
__global__ void build_T2_kernel(const float* __restrict__ coarse) {
    const int d = blockIdx.x;
    const int b = blockIdx.y;
    const int h = threadIdx.x;

    __shared__ float  Rs[NDIM][4];   // f32-quantized resize weights
    __shared__ float  Gf[16];        // f32-quantized gaussian taps
    __shared__ double Cs[192];       // coarse flow for this batch (f64)

    // --- cubic resize row h: sample position (h+0.5)/32 - 0.5, input size 4
    {
        double s = (h + 0.5) / 32.0 - 0.5;
        double w[4];
        double sum = 0.0;
        #pragma unroll
        for (int j = 0; j < 4; j++) {
            double x = fabs(s - (double)j);
            double v;
            if (x < 1.0)       v = ((1.5 * x - 2.5) * x) * x + 1.0;
            else if (x < 2.0)  v = ((-0.5 * x + 2.5) * x - 4.0) * x + 2.0;
            else               v = 0.0;
            w[j] = v;
            sum += v;
        }
        #pragma unroll
        for (int j = 0; j < 4; j++) Rs[h][j] = (float)(w[j] / sum);
    }

    // --- Gaussian taps: ax = -7..8, sigma = 2.5, normalized in f64 -> f32
    if (h < 16) {
        double Graw[16];
        double gs = 0.0;
        #pragma unroll
        for (int t = 0; t < 16; t++) {
            double a = (double)(t - 7);
            Graw[t] = exp(-a * a / (2.0 * 2.5 * 2.5));
            gs += Graw[t];
        }
        Gf[h] = (float)(Graw[h] / gs);
    }

    // --- coarse flow into shared (f64)
    for (int i = h; i < 192; i += blockDim.x) Cs[i] = (double)coarse[b * 192 + i];
    __syncthreads();

    // --- compose M rows in f64: M[x][j] = sum_t Gf[t] * Rs[x+t-7][j]
    double Mh[4], Md[4];
    #pragma unroll
    for (int j = 0; j < 4; j++) { Mh[j] = 0.0; Md[j] = 0.0; }
    #pragma unroll
    for (int t = 0; t < 16; t++) {
        const double g = (double)Gf[t];
        const int sh = h + t - 7;
        const int sd = d + t - 7;
        if (sh >= 0 && sh < NDIM) {
            #pragma unroll
            for (int j = 0; j < 4; j++) Mh[j] += g * (double)Rs[sh][j];
        }
        if (sd >= 0 && sd < NDIM) {
            #pragma unroll
            for (int j = 0; j < 4; j++) Md[j] += g * (double)Rs[sd][j];
        }
    }

    // publish Mgd for warp_kernel (one block is enough)
    if (d == 0 && b == 0) {
        #pragma unroll
        for (int j = 0; j < 4; j++) Mgd[h][j] = Mh[j];
    }

    // --- T2 contraction over (i=D-grid, j=H-grid) in f64
    double acc[4][3];
    #pragma unroll
    for (int k = 0; k < 4; k++)
        #pragma unroll
        for (int c = 0; c < 3; c++) acc[k][c] = 0.0;

    #pragma unroll
    for (int i = 0; i < 4; i++) {
        #pragma unroll
        for (int j = 0; j < 4; j++) {
            double wij = Md[i] * Mh[j];
            const double* cij = &Cs[(i * 4 + j) * 4 * 3];
            #pragma unroll
            for (int k = 0; k < 4; k++)
                #pragma unroll
                for (int c = 0; c < 3; c++)
                    acc[k][c] = fma(wij, cij[k * 3 + c], acc[k][c]);
        }
    }
    #pragma unroll
    for (int k = 0; k < 4; k++)
        #pragma unroll
        for (int c = 0; c < 3; c++)
            T2d[b][d][h][k][c] = acc[k][c];
}

// ---------------------------------------------------------------------------
// Main warp kernel. One thread per output voxel (b,d,h,w).
// block = (128, 2) -> w = tx, h = 2*blockIdx.x + ty; grid = (64, 128, 2).
// Flow contraction in f64 (12 DFMA) from T2d (uniform broadcast loads, no
// smem/sync), rounded once to f32, then the exact reference f32 roundings.
// Trilinear image sample (8 float4 gathers), nearest label.
// ---------------------------------------------------------------------------
__global__ __launch_bounds__(256) void warp_kernel(
    const float4* __restrict__ img,   // [B,D,H,W] of float4 (C=4)
    const int*    __restrict__ lab,   // [B,D,H,W]
    float*        __restrict__ out)   // image (float4) then label floats
{
    const int w = threadIdx.x;
    const int h = (blockIdx.x << 1) + threadIdx.y;
    const int d = blockIdx.y;
    const int b = blockIdx.z;

    // 12 uniform doubles (same address across warp -> broadcast)
    const double2* t2v = reinterpret_cast<const double2*>(&T2d[b][d][h][0][0]);
    const double2 p0 = t2v[0], p1 = t2v[1], p2 = t2v[2],
                  p3 = t2v[3], p4 = t2v[4], p5 = t2v[5];
    // layout: [k][c] row-major: t0..t11 = k0c0 k0c1 k0c2 k1c0 ...
    const double t0 = p0.x, t1 = p0.y, t2_ = p1.x, t3 = p1.y,
                 t4 = p2.x, t5 = p2.y, t6  = p3.x, t7 = p3.y,
                 t8 = p4.x, t9 = p4.y, t10 = p5.x, t11 = p5.y;

    const double2 mA = *reinterpret_cast<const double2*>(&Mgd[w][0]);
    const double2 mB = *reinterpret_cast<const double2*>(&Mgd[w][2]);

    // flow components (c: 0=d, 1=h, 2=w), k-contraction over M[w], f64
    const double fdd = mA.x * t0  + mA.y * t3  + mB.x * t6  + mB.y * t9;
    const double fhd = mA.x * t1  + mA.y * t4  + mB.x * t7  + mB.y * t10;
    const double fwd = mA.x * t2_ + mA.y * t5  + mB.x * t8  + mB.y * t11;

    // Replicate reference f32 roundings: flow(f32) -> *35 (f32) -> +grid (f32)
    const float wd = __fadd_rn((float)d, __fmul_rn(35.0f, (float)fdd));
    const float wh = __fadd_rn((float)h, __fmul_rn(35.0f, (float)fhd));
    const float ww = __fadd_rn((float)w, __fmul_rn(35.0f, (float)fwd));

    const float fdf = floorf(wd), fhf = floorf(wh), fwf = floorf(ww);
    const float td = wd - fdf, th = wh - fhf, tw = ww - fwf;

    const int d0 = min(max((int)fdf, 0), NDIM - 1);
    const int h0 = min(max((int)fhf, 0), NDIM - 1);
    const int w0 = min(max((int)fwf, 0), NDIM - 1);
    const int d1 = min(max((int)fdf + 1, 0), NDIM - 1);
    const int h1 = min(max((int)fhf + 1, 0), NDIM - 1);
    const int w1 = min(max((int)fwf + 1, 0), NDIM - 1);

    const int bb = b * NDIM;
    #define VIDX(di, hi, wi) ((((bb + (di)) * NDIM + (hi)) * NDIM) + (wi))

    // nearest-neighbor label gather issued first to overlap
    const int nd = min(max((int)rintf(wd), 0), NDIM - 1);
    const int nh = min(max((int)rintf(wh), 0), NDIM - 1);
    const int nw = min(max((int)rintf(ww), 0), NDIM - 1);
    const int lv = __ldg(&lab[VIDX(nd, nh, nw)]);

    const float4 v000 = __ldg(&img[VIDX(d0, h0, w0)]);
    const float4 v001 = __ldg(&img[VIDX(d0, h0, w1)]);
    const float4 v010 = __ldg(&img[VIDX(d0, h1, w0)]);
    const float4 v011 = __ldg(&img[VIDX(d0, h1, w1)]);
    const float4 v100 = __ldg(&img[VIDX(d1, h0, w0)]);
    const float4 v101 = __ldg(&img[VIDX(d1, h0, w1)]);
    const float4 v110 = __ldg(&img[VIDX(d1, h1, w0)]);
    const float4 v111 = __ldg(&img[VIDX(d1, h1, w1)]);

    const float omw = 1.0f - tw, omh = 1.0f - th, omd = 1.0f - td;

    float4 c00, c01, c10, c11, c0, c1, res;
    c00.x = v000.x * omw + v001.x * tw;  c00.y = v000.y * omw + v001.y * tw;
    c00.z = v000.z * omw + v001.z * tw;  c00.w = v000.w * omw + v001.w * tw;
    c01.x = v010.x * omw + v011.x * tw;  c01.y = v010.y * omw + v011.y * tw;
    c01.z = v010.z * omw + v011.z * tw;  c01.w = v010.w * omw + v011.w * tw;
    c10.x = v100.x * omw + v101.x * tw;  c10.y = v100.y * omw + v101.y * tw;
    c10.z = v100.z * omw + v101.z * tw;  c10.w = v100.w * omw + v101.w * tw;
    c11.x = v110.x * omw + v111.x * tw;  c11.y = v110.y * omw + v111.y * tw;
    c11.z = v110.z * omw + v111.z * tw;  c11.w = v110.w * omw + v111.w * tw;

    c0.x = c00.x * omh + c01.x * th;  c0.y = c00.y * omh + c01.y * th;
    c0.z = c00.z * omh + c01.z * th;  c0.w = c00.w * omh + c01.w * th;
    c1.x = c10.x * omh + c11.x * th;  c1.y = c10.y * omh + c11.y * th;
    c1.z = c10.z * omh + c11.z * th;  c1.w = c10.w * omh + c11.w * th;

    res.x = c0.x * omd + c1.x * td;  res.y = c0.y * omd + c1.y * td;
    res.z = c0.z * omd + c1.z * td;  res.w = c0.w * omd + c1.w * td;

    const int lin = VIDX(d, h, w);
    reinterpret_cast<float4*>(out)[lin] = res;
    out[IMG_ELEMS + lin] = (float)lv;
    #undef VIDX
}

// ---------------------------------------------------------------------------
// kernel_launch — graph-capturable, allocation-free
// ---------------------------------------------------------------------------
extern "C" void kernel_launch(void* const* d_in, const int* in_sizes, int n_in,
                              void* d_out, int out_size) {
    const float4* img    = (const float4*)d_in[0];  // image_volume [2,128,128,128,4] f32
    const int*    lab    = (const int*)d_in[1];     // label_volume [2,128,128,128,1] i32
    const float*  coarse = (const float*)d_in[2];   // coarse_flow  [2,4,4,4,3] f32
    float*        out    = (float*)d_out;

    build_T2_kernel<<<dim3(NDIM, NB), NDIM>>>(coarse);
    warp_kernel<<<dim3(NDIM / 2, NDIM, NB), dim3(NDIM, 2)>>>(img, lab, out);
}